// round 8
// baseline (speedup 1.0000x reference)
#include <cuda_runtime.h>
#include <math.h>

#define Nn    1024
#define Hh    4
#define Ff    32
#define CH    128     // H*F
#define DINC  128
#define DE    32
#define EPSB  1e-5f
#define SLOPE 0.2f

// ---------------- scratch (no allocs allowed) ----------------
__device__ __align__(16) float g_nproj[Nn * CH];
__device__ __align__(16) float g_skip [Nn * CH];
__device__ float g_ssrc [Nn * Hh];
__device__ float g_stgt [Nn * Hh];
__device__ __align__(16) float g_Y    [Nn * CH];
__device__ __align__(16) float g_mu   [CH];
__device__ __align__(16) float g_rstd [CH];
__device__ __align__(16) float g_Wr   [DE * CH];  // [k][lane*4+q] = W_edge[k][q*32+lane]
__device__ float g_p1   [32 * CH];
__device__ float g_p2   [32 * CH];
__device__ unsigned g_ctr;
__device__ unsigned g_done;
__device__ volatile int g_flag;

__device__ __forceinline__ float lrelu(float v) { return v > 0.f ? v : SLOPE * v; }

// ---- Blackwell packed f32x2 helpers ----
__device__ __forceinline__ unsigned long long fma2(unsigned long long a,
                                                   unsigned long long b,
                                                   unsigned long long c) {
    unsigned long long d;
    asm("fma.rn.f32x2 %0, %1, %2, %3;" : "=l"(d) : "l"(a), "l"(b), "l"(c));
    return d;
}
__device__ __forceinline__ unsigned long long dup2(float x) {
    unsigned long long r;
    unsigned xi = __float_as_uint(x);
    asm("mov.b64 %0, {%1, %1};" : "=l"(r) : "r"(xi));
    return r;
}
union U64F2 { unsigned long long u; float2 f; };

// ---------------------------------------------------------------------------
// k1: nproj = x@W_proj, skip = x@W_skip, s_src/s_tgt per-head dots.
// 128 blocks x 8 rows. Warp w: matrix m=w&1 (0=proj,1=skip), row pair
// rh=w>>1; lane = channel-quad c4. W loaded as LDG.128 in explicit batches
// of 8 (MLP=8); x staged as packed row-pairs (one LDS.64 broadcast/iter).
// 8 independent FMA chains per thread. Block 127 swizzles W_edge -> g_Wr.
// ---------------------------------------------------------------------------
__global__ __launch_bounds__(256) void k1_proj(
    const float* __restrict__ x,
    const float* __restrict__ Wp,
    const float* __restrict__ Wsk,
    const float* __restrict__ a_src,
    const float* __restrict__ a_tgt,
    const float* __restrict__ W_edge)
{
    __shared__ __align__(16) float2 xsp[DINC][4];   // [k][rh] = {x[r0][k], x[r1][k]}
    const int tid  = threadIdx.x;
    const int lane = tid & 31;        // c4: channels lane*4 .. lane*4+3
    const int w    = tid >> 5;
    const int m    = w & 1;
    const int rh   = w >> 1;          // 0..3
    const int i0   = blockIdx.x * 8;

    for (int idx = tid; idx < 8 * DINC; idx += 256) {
        const int r = idx >> 7, k = idx & 127;
        reinterpret_cast<float*>(&xsp[k][r >> 1])[r & 1] = x[i0 * DINC + idx];
    }
    if (blockIdx.x == 127) {          // one-time W_edge swizzle for k2
        for (int idx = tid; idx < DE * CH; idx += 256) {
            const int k = idx >> 7, cc = idx & 127;
            g_Wr[k * CH + (cc & 31) * 4 + (cc >> 5)] = W_edge[idx];
        }
    }
    __syncthreads();

    const float4* __restrict__ W4 =
        reinterpret_cast<const float4*>(m ? Wsk : Wp);  // W4[k*32 + lane]

    float4 acc0 = make_float4(0.f, 0.f, 0.f, 0.f);
    float4 acc1 = make_float4(0.f, 0.f, 0.f, 0.f);

    #pragma unroll 1
    for (int k0 = 0; k0 < DINC; k0 += 8) {
        float4 wv[8];
        float2 xv[8];
        #pragma unroll
        for (int u = 0; u < 8; u++) wv[u] = __ldg(&W4[(k0 + u) * 32 + lane]);
        #pragma unroll
        for (int u = 0; u < 8; u++) xv[u] = xsp[k0 + u][rh];
        #pragma unroll
        for (int u = 0; u < 8; u++) {
            acc0.x = fmaf(xv[u].x, wv[u].x, acc0.x);
            acc0.y = fmaf(xv[u].x, wv[u].y, acc0.y);
            acc0.z = fmaf(xv[u].x, wv[u].z, acc0.z);
            acc0.w = fmaf(xv[u].x, wv[u].w, acc0.w);
            acc1.x = fmaf(xv[u].y, wv[u].x, acc1.x);
            acc1.y = fmaf(xv[u].y, wv[u].y, acc1.y);
            acc1.z = fmaf(xv[u].y, wv[u].z, acc1.z);
            acc1.w = fmaf(xv[u].y, wv[u].w, acc1.w);
        }
    }

    const int r0 = i0 + rh * 2;
    float4* __restrict__ dst = reinterpret_cast<float4*>(m ? g_skip : g_nproj);
    dst[(r0 + 0) * 32 + lane] = acc0;
    dst[(r0 + 1) * 32 + lane] = acc1;

    if (m == 0) {   // per-head attention dots for both rows
        const float4 av  = reinterpret_cast<const float4*>(a_src)[lane];
        const float4 atv = reinterpret_cast<const float4*>(a_tgt)[lane];
        const int h = lane >> 3;
        float s1a = acc0.x*av.x  + acc0.y*av.y  + acc0.z*av.z  + acc0.w*av.w;
        float s2a = acc0.x*atv.x + acc0.y*atv.y + acc0.z*atv.z + acc0.w*atv.w;
        float s1b = acc1.x*av.x  + acc1.y*av.y  + acc1.z*av.z  + acc1.w*av.w;
        float s2b = acc1.x*atv.x + acc1.y*atv.y + acc1.z*atv.z + acc1.w*atv.w;
        #pragma unroll
        for (int o = 4; o > 0; o >>= 1) {   // reduce within 8-lane head group
            s1a += __shfl_xor_sync(0xffffffffu, s1a, o);
            s2a += __shfl_xor_sync(0xffffffffu, s2a, o);
            s1b += __shfl_xor_sync(0xffffffffu, s1b, o);
            s2b += __shfl_xor_sync(0xffffffffu, s2b, o);
        }
        if ((lane & 7) == 0) {
            g_ssrc[(r0 + 0) * Hh + h] = s1a;
            g_stgt[(r0 + 0) * Hh + h] = s2a;
            g_ssrc[(r0 + 1) * Hh + h] = s1b;
            g_stgt[(r0 + 1) * Hh + h] = s2b;
        }
    }
}

// ---------------------------------------------------------------------------
// k2: per-row sparse attention, one block per row i.
//  - deterministic parallel compaction of active j (conn==0 <=> edge; -1e9
//    edges have bit-exact-zero softmax weight in fp32, matching reference)
//  - 8 warps x 8-edge batches; matvec in packed f32x2 (edge pairs), edges
//    staged in smem so LDS.64 yields packed pairs for free
//  - no max-subtraction softmax (scores O(1)); reduce-and-distribute tree
//    lands sed per head on lane groups -> parallel expf + coalesced
//    LDG.128 nproj gather (4 channels/lane)
// ---------------------------------------------------------------------------
__global__ __launch_bounds__(256) void k2_attn(
    const float* __restrict__ e,
    const float* __restrict__ conn,
    const float* __restrict__ b_edge,
    const float* __restrict__ a_edge)
{
    __shared__ int   jlist[Nn];
    __shared__ int   wcnt[8], woff[8];
    __shared__ int   nact_s;
    __shared__ float ssrc_s[Hh];
    __shared__ __align__(16) float es[8][DE * 10];   // [warp][k*10+b]
    __shared__ float4 acc_sm[8][32];
    __shared__ float  l_sm[8][Hh];

    const int tid  = threadIdx.x;
    const int lane = tid & 31;
    const int w    = tid >> 5;
    const int i    = blockIdx.x;

    if (tid < Hh) ssrc_s[tid] = g_ssrc[i * Hh + tid];

    // --- deterministic compaction: warp w scans j in [w*128, w*128+128) ---
    int  pos[4];
    bool on[4];
    {
        int cnt = 0;
        #pragma unroll
        for (int r = 0; r < 4; r++) {
            const int j = w * 128 + r * 32 + lane;
            on[r] = conn[i * Nn + j] > -1e8f;
            const unsigned bal = __ballot_sync(0xffffffffu, on[r]);
            pos[r] = cnt + __popc(bal & ((1u << lane) - 1u));
            cnt += __popc(bal);
        }
        if (lane == 0) wcnt[w] = cnt;
    }
    __syncthreads();
    if (tid == 0) {
        int acc = 0;
        #pragma unroll
        for (int ww = 0; ww < 8; ww++) { woff[ww] = acc; acc += wcnt[ww]; }
        nact_s = acc;
    }
    __syncthreads();
    {
        const int off = woff[w];
        #pragma unroll
        for (int r = 0; r < 4; r++)
            if (on[r]) jlist[off + pos[r]] = w * 128 + r * 32 + lane;
    }
    __syncthreads();
    const int nact = nact_s;

    const float4* __restrict__ Wr4 = reinterpret_cast<const float4*>(g_Wr);
    const float4 bev = make_float4(b_edge[lane], b_edge[32 + lane],
                                   b_edge[64 + lane], b_edge[96 + lane]);
    const float4 aev = make_float4(a_edge[lane], a_edge[32 + lane],
                                   a_edge[64 + lane], a_edge[96 + lane]);
    const int   head  = lane >> 3;
    const float src_h = ssrc_s[head];
    const bool  hi16  = (lane & 16) != 0;
    const bool  hi8   = (lane & 8)  != 0;

    float4 oacc = make_float4(0.f, 0.f, 0.f, 0.f);
    float  lacc = 0.f;
    float* esw  = es[w];

    for (int base = w * 8; base < nact; base += 64) {
        int  jj[8];
        bool act[8];
        #pragma unroll
        for (int b = 0; b < 8; b++) {
            const int idx = base + b;
            act[b] = idx < nact;
            jj[b]  = jlist[act[b] ? idx : (nact - 1)];
        }

        __syncwarp();
        #pragma unroll
        for (int b = 0; b < 8; b++)
            esw[lane * 10 + b] = __ldg(&e[((long)i * Nn + jj[b]) * DE + lane]);
        __syncwarp();

        unsigned long long acc2[4][4];
        #pragma unroll
        for (int q = 0; q < 4; q++)
            #pragma unroll
            for (int t = 0; t < 4; t++) acc2[q][t] = 0ull;

        #pragma unroll 8
        for (int k = 0; k < DE; k++) {
            const float4 wv = __ldg(&Wr4[k * 32 + lane]);
            const unsigned long long wx = dup2(wv.x), wy = dup2(wv.y),
                                     wz = dup2(wv.z), ww2 = dup2(wv.w);
            #pragma unroll
            for (int t = 0; t < 4; t++) {
                const unsigned long long ee =
                    *reinterpret_cast<const unsigned long long*>(&esw[k * 10 + 2 * t]);
                acc2[0][t] = fma2(ee, wx,  acc2[0][t]);
                acc2[1][t] = fma2(ee, wy,  acc2[1][t]);
                acc2[2][t] = fma2(ee, wz,  acc2[2][t]);
                acc2[3][t] = fma2(ee, ww2, acc2[3][t]);
            }
        }

        #pragma unroll
        for (int b = 0; b < 8; b++) {
            const int t = b >> 1;
            U64F2 c0, c1, c2, c3;
            c0.u = acc2[0][t]; c1.u = acc2[1][t]; c2.u = acc2[2][t]; c3.u = acc2[3][t];
            const float s0 = (b & 1) ? c0.f.y : c0.f.x;
            const float s1 = (b & 1) ? c1.f.y : c1.f.x;
            const float s2 = (b & 1) ? c2.f.y : c2.f.x;
            const float s3 = (b & 1) ? c3.f.y : c3.f.x;

            const float a0 = lrelu(s0 + bev.x) * aev.x;
            const float a1 = lrelu(s1 + bev.y) * aev.y;
            const float a2 = lrelu(s2 + bev.z) * aev.z;
            const float a3 = lrelu(s3 + bev.w) * aev.w;

            float x0 = hi16 ? a2 : a0;
            float x1 = hi16 ? a3 : a1;
            const float y0 = hi16 ? a0 : a2;
            const float y1 = hi16 ? a1 : a3;
            x0 += __shfl_xor_sync(0xffffffffu, y0, 16);
            x1 += __shfl_xor_sync(0xffffffffu, y1, 16);
            float r = (hi8 ? x1 : x0) + __shfl_xor_sync(0xffffffffu, hi8 ? x0 : x1, 8);
            r += __shfl_xor_sync(0xffffffffu, r, 4);
            r += __shfl_xor_sync(0xffffffffu, r, 2);
            r += __shfl_xor_sync(0xffffffffu, r, 1);

            const float stg = __ldg(&g_stgt[jj[b] * Hh + head]);
            const float sc  = lrelu(src_h + stg + r);
            const float p   = act[b] ? __expf(sc) : 0.f;
            lacc += p;
            const float4 nv =
                __ldg(reinterpret_cast<const float4*>(&g_nproj[(long)jj[b] * CH + lane * 4]));
            oacc.x = fmaf(p, nv.x, oacc.x);
            oacc.y = fmaf(p, nv.y, oacc.y);
            oacc.z = fmaf(p, nv.z, oacc.z);
            oacc.w = fmaf(p, nv.w, oacc.w);
        }
    }

    acc_sm[w][lane] = oacc;
    if ((lane & 7) == 0) l_sm[w][head] = lacc;
    __syncthreads();

    if (tid < 32) {
        float4 V = make_float4(0.f, 0.f, 0.f, 0.f);
        float  L = 0.f;
        const int hq = lane >> 3;
        #pragma unroll
        for (int ww = 0; ww < 8; ww++) {
            const float4 a = acc_sm[ww][lane];
            V.x += a.x; V.y += a.y; V.z += a.z; V.w += a.w;
            L   += l_sm[ww][hq];
        }
        const float invL = 1.f / L;
        const float4 sk = *reinterpret_cast<const float4*>(&g_skip[i * CH + lane * 4]);
        float4 yv;
        yv.x = fmaf(V.x, invL, sk.x);
        yv.y = fmaf(V.y, invL, sk.y);
        yv.z = fmaf(V.z, invL, sk.z);
        yv.w = fmaf(V.w, invL, sk.w);
        *reinterpret_cast<float4*>(&g_Y[i * CH + lane * 4]) = yv;
    }
}

// ---------------------------------------------------------------------------
// k34: fused batch-stats + BN apply + ELU. 32 resident blocks, flag spin.
// ---------------------------------------------------------------------------
__global__ __launch_bounds__(256) void k34_bn(
    const float* __restrict__ gamma,
    const float* __restrict__ beta,
    const float* __restrict__ bias,
    float* __restrict__ out)
{
    const int b    = blockIdx.x;
    const int tid  = threadIdx.x;
    const int c    = tid & 127;
    const int half = tid >> 7;

    float s = 0.f, s2 = 0.f;
    const int r0 = b * 32 + half * 16;
    #pragma unroll 4
    for (int r = 0; r < 16; r++) {
        const float v = g_Y[(r0 + r) * CH + c];
        s += v;
        s2 = fmaf(v, v, s2);
    }

    __shared__ float sh1[CH], sh2[CH];
    __shared__ int   amlast;
    if (half == 1) { sh1[c] = s; sh2[c] = s2; }
    __syncthreads();
    if (half == 0) {
        g_p1[b * CH + c] = s  + sh1[c];
        g_p2[b * CH + c] = s2 + sh2[c];
    }
    __threadfence();
    __syncthreads();
    if (tid == 0) amlast = (atomicAdd(&g_ctr, 1u) == 31u);
    __syncthreads();

    if (amlast) {
        if (tid < CH) {
            float S = 0.f, S2 = 0.f;
            #pragma unroll
            for (int bb = 0; bb < 32; bb++) {
                S  += g_p1[bb * CH + tid];
                S2 += g_p2[bb * CH + tid];
            }
            const float mu  = S  * (1.f / Nn);
            const float var = S2 * (1.f / Nn) - mu * mu;
            g_mu[tid]   = mu;
            g_rstd[tid] = rsqrtf(var + EPSB);
        }
        __threadfence();
        __syncthreads();
        if (tid == 0) g_flag = 1;
    }

    if (tid == 0) { while (g_flag == 0) __nanosleep(64); }
    __syncthreads();
    __threadfence();

    #pragma unroll
    for (int rr = 0; rr < 4; rr++) {
        const int idx4 = b * 1024 + rr * 256 + tid;
        const int c4   = idx4 & 31;
        const float4 v  = reinterpret_cast<const float4*>(g_Y)[idx4];
        const float4 mu = reinterpret_cast<const float4*>(g_mu)[c4];
        const float4 rs = reinterpret_cast<const float4*>(g_rstd)[c4];
        const float4 ga = reinterpret_cast<const float4*>(gamma)[c4];
        const float4 be = reinterpret_cast<const float4*>(beta)[c4];
        const float4 bi = reinterpret_cast<const float4*>(bias)[c4];
        float4 r; float o;
        o = fmaf((v.x - mu.x) * rs.x, ga.x, be.x) + bi.x;  r.x = o > 0.f ? o : expm1f(o);
        o = fmaf((v.y - mu.y) * rs.y, ga.y, be.y) + bi.y;  r.y = o > 0.f ? o : expm1f(o);
        o = fmaf((v.z - mu.z) * rs.z, ga.z, be.z) + bi.z;  r.z = o > 0.f ? o : expm1f(o);
        o = fmaf((v.w - mu.w) * rs.w, ga.w, be.w) + bi.w;  r.w = o > 0.f ? o : expm1f(o);
        reinterpret_cast<float4*>(out)[idx4] = r;
    }

    __syncthreads();
    if (tid == 0) {
        if (atomicAdd(&g_done, 1u) == 31u) {
            g_ctr  = 0u;
            g_done = 0u;
            g_flag = 0;
        }
    }
}

// ---------------------------------------------------------------------------
extern "C" void kernel_launch(void* const* d_in, const int* in_sizes, int n_in,
                              void* d_out, int out_size)
{
    const float* x     = (const float*)d_in[0];
    const float* e     = (const float*)d_in[1];
    const float* conn  = (const float*)d_in[2];
    const float* Wp    = (const float*)d_in[3];
    const float* We    = (const float*)d_in[4];
    const float* be    = (const float*)d_in[5];
    const float* asrc  = (const float*)d_in[6];
    const float* atgt  = (const float*)d_in[7];
    const float* aedg  = (const float*)d_in[8];
    const float* Wsk   = (const float*)d_in[9];
    const float* gamma = (const float*)d_in[10];
    const float* beta  = (const float*)d_in[11];
    const float* bias  = (const float*)d_in[12];
    float* out = (float*)d_out;

    k1_proj<<<Nn / 8, 256>>>(x, Wp, Wsk, asrc, atgt, We);
    k2_attn<<<Nn, 256>>>(e, conn, be, aedg);
    k34_bn<<<32, 256>>>(gamma, beta, bias, out);
}

// round 10
// speedup vs baseline: 1.0952x; 1.0952x over previous
#include <cuda_runtime.h>
#include <math.h>

#define Nn    1024
#define Hh    4
#define Ff    32
#define CH    128     // H*F
#define DINC  128
#define DE    32
#define EPSB  1e-5f
#define SLOPE 0.2f

// ---------------- scratch (no allocs allowed) ----------------
__device__ __align__(16) float g_nproj[Nn * CH];
__device__ __align__(16) float g_skip [Nn * CH];
__device__ float g_ssrc [Nn * Hh];
__device__ float g_stgt [Nn * Hh];
__device__ __align__(16) float g_Y    [Nn * CH];
__device__ __align__(16) float g_mu   [CH];
__device__ __align__(16) float g_rstd [CH];
__device__ __align__(16) float g_Wr   [DE * CH];  // [k][lane*4+q] = W_edge[k][q*32+lane]
__device__ float g_p1   [32 * CH];
__device__ float g_p2   [32 * CH];
__device__ unsigned g_ctr;
__device__ unsigned g_done;
__device__ volatile int g_flag;

__device__ __forceinline__ float lrelu(float v) { return v > 0.f ? v : SLOPE * v; }

// ---- Blackwell packed f32x2 helpers ----
__device__ __forceinline__ unsigned long long fma2(unsigned long long a,
                                                   unsigned long long b,
                                                   unsigned long long c) {
    unsigned long long d;
    asm("fma.rn.f32x2 %0, %1, %2, %3;" : "=l"(d) : "l"(a), "l"(b), "l"(c));
    return d;
}
__device__ __forceinline__ unsigned long long dup2(float x) {
    unsigned long long r;
    unsigned xi = __float_as_uint(x);
    asm("mov.b64 %0, {%1, %1};" : "=l"(r) : "r"(xi));
    return r;
}
union U64F2 { unsigned long long u; float2 f; };

// ---------------------------------------------------------------------------
// k1: nproj = x@W_proj, skip = x@W_skip, s_src/s_tgt per-head dots.
// Split-K x4: 256 blocks x 4 rows. Thread (g, m, lane): K-group g (32 iters),
// matrix m, channel-quad lane. Only 32-deep serial LDG chain per thread;
// partials combined via smem by a (row, matrix, lane) warp remap.
// Block 255 swizzles W_edge -> g_Wr for k2.
// ---------------------------------------------------------------------------
__global__ __launch_bounds__(256) void k1_proj(
    const float* __restrict__ x,
    const float* __restrict__ Wp,
    const float* __restrict__ Wsk,
    const float* __restrict__ a_src,
    const float* __restrict__ a_tgt,
    const float* __restrict__ W_edge)
{
    __shared__ __align__(16) float4 xsT4[DINC];      // [k] = {x[r0..r3][k]}
    __shared__ __align__(16) float4 part[4][64][4];  // [g][m*32+lane][r]  16KB
    const int tid  = threadIdx.x;
    const int lane = tid & 31;
    const int m    = (tid >> 5) & 1;
    const int g    = tid >> 6;          // K-group 0..3
    const int i0   = blockIdx.x * 4;

    // stage x transposed: idx = r*128 + k
    for (int idx = tid; idx < 4 * DINC; idx += 256) {
        const int r = idx >> 7, k = idx & 127;
        reinterpret_cast<float*>(&xsT4[k])[r] = x[i0 * DINC + idx];
    }
    if (blockIdx.x == 255) {            // one-time W_edge swizzle for k2
        for (int idx = tid; idx < DE * CH; idx += 256) {
            const int k = idx >> 7, cc = idx & 127;
            g_Wr[k * CH + (cc & 31) * 4 + (cc >> 5)] = W_edge[idx];
        }
    }
    __syncthreads();

    const float4* __restrict__ W4 =
        reinterpret_cast<const float4*>(m ? Wsk : Wp);   // W4[k*32 + lane]

    float4 acc0 = make_float4(0.f,0.f,0.f,0.f);
    float4 acc1 = make_float4(0.f,0.f,0.f,0.f);
    float4 acc2 = make_float4(0.f,0.f,0.f,0.f);
    float4 acc3 = make_float4(0.f,0.f,0.f,0.f);

    const int kbeg = g * 32;
    #pragma unroll 4
    for (int kk = 0; kk < 32; kk++) {
        const int k = kbeg + kk;
        const float4 wv = __ldg(&W4[k * 32 + lane]);
        const float4 xv = xsT4[k];
        acc0.x = fmaf(xv.x, wv.x, acc0.x); acc0.y = fmaf(xv.x, wv.y, acc0.y);
        acc0.z = fmaf(xv.x, wv.z, acc0.z); acc0.w = fmaf(xv.x, wv.w, acc0.w);
        acc1.x = fmaf(xv.y, wv.x, acc1.x); acc1.y = fmaf(xv.y, wv.y, acc1.y);
        acc1.z = fmaf(xv.y, wv.z, acc1.z); acc1.w = fmaf(xv.y, wv.w, acc1.w);
        acc2.x = fmaf(xv.z, wv.x, acc2.x); acc2.y = fmaf(xv.z, wv.y, acc2.y);
        acc2.z = fmaf(xv.z, wv.z, acc2.z); acc2.w = fmaf(xv.z, wv.w, acc2.w);
        acc3.x = fmaf(xv.w, wv.x, acc3.x); acc3.y = fmaf(xv.w, wv.y, acc3.y);
        acc3.z = fmaf(xv.w, wv.z, acc3.z); acc3.w = fmaf(xv.w, wv.w, acc3.w);
    }

    const int slot = m * 32 + lane;
    part[g][slot][0] = acc0;
    part[g][slot][1] = acc1;
    part[g][slot][2] = acc2;
    part[g][slot][3] = acc3;
    __syncthreads();

    // combine remap: warp = (row r, matrix m2); lanes = 32 channel-quads
    const int r     = tid >> 6;
    const int m2    = (tid >> 5) & 1;
    const int slot2 = m2 * 32 + lane;
    float4 a = part[0][slot2][r];
    const float4 p1 = part[1][slot2][r];
    const float4 p2 = part[2][slot2][r];
    const float4 p3 = part[3][slot2][r];
    a.x += p1.x + p2.x + p3.x;
    a.y += p1.y + p2.y + p3.y;
    a.z += p1.z + p2.z + p3.z;
    a.w += p1.w + p2.w + p3.w;

    float4* __restrict__ dst = reinterpret_cast<float4*>(m2 ? g_skip : g_nproj);
    dst[(i0 + r) * 32 + lane] = a;

    if (m2 == 0) {   // per-head attention dots for this row
        const float4 av  = reinterpret_cast<const float4*>(a_src)[lane];
        const float4 atv = reinterpret_cast<const float4*>(a_tgt)[lane];
        const int h = lane >> 3;
        float s1 = a.x*av.x  + a.y*av.y  + a.z*av.z  + a.w*av.w;
        float s2 = a.x*atv.x + a.y*atv.y + a.z*atv.z + a.w*atv.w;
        #pragma unroll
        for (int o = 4; o > 0; o >>= 1) {   // reduce within 8-lane head group
            s1 += __shfl_xor_sync(0xffffffffu, s1, o);
            s2 += __shfl_xor_sync(0xffffffffu, s2, o);
        }
        if ((lane & 7) == 0) {
            g_ssrc[(i0 + r) * Hh + h] = s1;
            g_stgt[(i0 + r) * Hh + h] = s2;
        }
    }
}

// ---------------------------------------------------------------------------
// k2: per-row sparse attention, one block per row i.
//  - deterministic parallel compaction of active j (conn==0 <=> edge; -1e9
//    edges have bit-exact-zero softmax weight in fp32, matching reference)
//  - 8 warps x 8-edge batches; matvec in packed f32x2 (edge pairs), edges
//    staged in smem so LDS.64 yields packed pairs for free
//  - no max-subtraction softmax (scores O(1)); reduce-and-distribute tree
//    lands sed per head on lane groups -> parallel expf + coalesced
//    LDG.128 nproj gather (4 channels/lane)
// ---------------------------------------------------------------------------
__global__ __launch_bounds__(256) void k2_attn(
    const float* __restrict__ e,
    const float* __restrict__ conn,
    const float* __restrict__ b_edge,
    const float* __restrict__ a_edge)
{
    __shared__ int   jlist[Nn];
    __shared__ int   wcnt[8], woff[8];
    __shared__ int   nact_s;
    __shared__ float ssrc_s[Hh];
    __shared__ __align__(16) float es[8][DE * 10];   // [warp][k*10+b]
    __shared__ float4 acc_sm[8][32];
    __shared__ float  l_sm[8][Hh];

    const int tid  = threadIdx.x;
    const int lane = tid & 31;
    const int w    = tid >> 5;
    const int i    = blockIdx.x;

    if (tid < Hh) ssrc_s[tid] = g_ssrc[i * Hh + tid];

    // --- deterministic compaction: warp w scans j in [w*128, w*128+128) ---
    int  pos[4];
    bool on[4];
    {
        int cnt = 0;
        #pragma unroll
        for (int r = 0; r < 4; r++) {
            const int j = w * 128 + r * 32 + lane;
            on[r] = conn[i * Nn + j] > -1e8f;
            const unsigned bal = __ballot_sync(0xffffffffu, on[r]);
            pos[r] = cnt + __popc(bal & ((1u << lane) - 1u));
            cnt += __popc(bal);
        }
        if (lane == 0) wcnt[w] = cnt;
    }
    __syncthreads();
    if (tid == 0) {
        int acc = 0;
        #pragma unroll
        for (int ww = 0; ww < 8; ww++) { woff[ww] = acc; acc += wcnt[ww]; }
        nact_s = acc;
    }
    __syncthreads();
    {
        const int off = woff[w];
        #pragma unroll
        for (int r = 0; r < 4; r++)
            if (on[r]) jlist[off + pos[r]] = w * 128 + r * 32 + lane;
    }
    __syncthreads();
    const int nact = nact_s;

    const float4* __restrict__ Wr4 = reinterpret_cast<const float4*>(g_Wr);
    const float4 bev = make_float4(b_edge[lane], b_edge[32 + lane],
                                   b_edge[64 + lane], b_edge[96 + lane]);
    const float4 aev = make_float4(a_edge[lane], a_edge[32 + lane],
                                   a_edge[64 + lane], a_edge[96 + lane]);
    const int   head  = lane >> 3;
    const float src_h = ssrc_s[head];
    const bool  hi16  = (lane & 16) != 0;
    const bool  hi8   = (lane & 8)  != 0;

    float4 oacc = make_float4(0.f, 0.f, 0.f, 0.f);
    float  lacc = 0.f;
    float* esw  = es[w];

    for (int base = w * 8; base < nact; base += 64) {
        int  jj[8];
        bool act[8];
        #pragma unroll
        for (int b = 0; b < 8; b++) {
            const int idx = base + b;
            act[b] = idx < nact;
            jj[b]  = jlist[act[b] ? idx : (nact - 1)];
        }

        __syncwarp();
        #pragma unroll
        for (int b = 0; b < 8; b++)
            esw[lane * 10 + b] = __ldg(&e[((long)i * Nn + jj[b]) * DE + lane]);
        __syncwarp();

        unsigned long long acc2[4][4];
        #pragma unroll
        for (int q = 0; q < 4; q++)
            #pragma unroll
            for (int t = 0; t < 4; t++) acc2[q][t] = 0ull;

        #pragma unroll 8
        for (int k = 0; k < DE; k++) {
            const float4 wv = __ldg(&Wr4[k * 32 + lane]);
            const unsigned long long wx = dup2(wv.x), wy = dup2(wv.y),
                                     wz = dup2(wv.z), ww2 = dup2(wv.w);
            #pragma unroll
            for (int t = 0; t < 4; t++) {
                const unsigned long long ee =
                    *reinterpret_cast<const unsigned long long*>(&esw[k * 10 + 2 * t]);
                acc2[0][t] = fma2(ee, wx,  acc2[0][t]);
                acc2[1][t] = fma2(ee, wy,  acc2[1][t]);
                acc2[2][t] = fma2(ee, wz,  acc2[2][t]);
                acc2[3][t] = fma2(ee, ww2, acc2[3][t]);
            }
        }

        #pragma unroll
        for (int b = 0; b < 8; b++) {
            const int t = b >> 1;
            U64F2 c0, c1, c2, c3;
            c0.u = acc2[0][t]; c1.u = acc2[1][t]; c2.u = acc2[2][t]; c3.u = acc2[3][t];
            const float s0 = (b & 1) ? c0.f.y : c0.f.x;
            const float s1 = (b & 1) ? c1.f.y : c1.f.x;
            const float s2 = (b & 1) ? c2.f.y : c2.f.x;
            const float s3 = (b & 1) ? c3.f.y : c3.f.x;

            const float a0 = lrelu(s0 + bev.x) * aev.x;
            const float a1 = lrelu(s1 + bev.y) * aev.y;
            const float a2 = lrelu(s2 + bev.z) * aev.z;
            const float a3 = lrelu(s3 + bev.w) * aev.w;

            float x0 = hi16 ? a2 : a0;
            float x1 = hi16 ? a3 : a1;
            const float y0 = hi16 ? a0 : a2;
            const float y1 = hi16 ? a1 : a3;
            x0 += __shfl_xor_sync(0xffffffffu, y0, 16);
            x1 += __shfl_xor_sync(0xffffffffu, y1, 16);
            float r = (hi8 ? x1 : x0) + __shfl_xor_sync(0xffffffffu, hi8 ? x0 : x1, 8);
            r += __shfl_xor_sync(0xffffffffu, r, 4);
            r += __shfl_xor_sync(0xffffffffu, r, 2);
            r += __shfl_xor_sync(0xffffffffu, r, 1);

            const float stg = __ldg(&g_stgt[jj[b] * Hh + head]);
            const float sc  = lrelu(src_h + stg + r);
            const float p   = act[b] ? __expf(sc) : 0.f;
            lacc += p;
            const float4 nv =
                __ldg(reinterpret_cast<const float4*>(&g_nproj[(long)jj[b] * CH + lane * 4]));
            oacc.x = fmaf(p, nv.x, oacc.x);
            oacc.y = fmaf(p, nv.y, oacc.y);
            oacc.z = fmaf(p, nv.z, oacc.z);
            oacc.w = fmaf(p, nv.w, oacc.w);
        }
    }

    acc_sm[w][lane] = oacc;
    if ((lane & 7) == 0) l_sm[w][head] = lacc;
    __syncthreads();

    if (tid < 32) {
        float4 V = make_float4(0.f, 0.f, 0.f, 0.f);
        float  L = 0.f;
        const int hq = lane >> 3;
        #pragma unroll
        for (int ww = 0; ww < 8; ww++) {
            const float4 a = acc_sm[ww][lane];
            V.x += a.x; V.y += a.y; V.z += a.z; V.w += a.w;
            L   += l_sm[ww][hq];
        }
        const float invL = 1.f / L;
        const float4 sk = *reinterpret_cast<const float4*>(&g_skip[i * CH + lane * 4]);
        float4 yv;
        yv.x = fmaf(V.x, invL, sk.x);
        yv.y = fmaf(V.y, invL, sk.y);
        yv.z = fmaf(V.z, invL, sk.z);
        yv.w = fmaf(V.w, invL, sk.w);
        *reinterpret_cast<float4*>(&g_Y[i * CH + lane * 4]) = yv;
    }
}

// ---------------------------------------------------------------------------
// k34: fused batch-stats + BN apply + ELU. 32 resident blocks, flag spin.
// ---------------------------------------------------------------------------
__global__ __launch_bounds__(256) void k34_bn(
    const float* __restrict__ gamma,
    const float* __restrict__ beta,
    const float* __restrict__ bias,
    float* __restrict__ out)
{
    const int b    = blockIdx.x;
    const int tid  = threadIdx.x;
    const int c    = tid & 127;
    const int half = tid >> 7;

    float s = 0.f, s2 = 0.f;
    const int r0 = b * 32 + half * 16;
    #pragma unroll 4
    for (int r = 0; r < 16; r++) {
        const float v = g_Y[(r0 + r) * CH + c];
        s += v;
        s2 = fmaf(v, v, s2);
    }

    __shared__ float sh1[CH], sh2[CH];
    __shared__ int   amlast;
    if (half == 1) { sh1[c] = s; sh2[c] = s2; }
    __syncthreads();
    if (half == 0) {
        g_p1[b * CH + c] = s  + sh1[c];
        g_p2[b * CH + c] = s2 + sh2[c];
    }
    __threadfence();
    __syncthreads();
    if (tid == 0) amlast = (atomicAdd(&g_ctr, 1u) == 31u);
    __syncthreads();

    if (amlast) {
        if (tid < CH) {
            float S = 0.f, S2 = 0.f;
            #pragma unroll
            for (int bb = 0; bb < 32; bb++) {
                S  += g_p1[bb * CH + tid];
                S2 += g_p2[bb * CH + tid];
            }
            const float mu  = S  * (1.f / Nn);
            const float var = S2 * (1.f / Nn) - mu * mu;
            g_mu[tid]   = mu;
            g_rstd[tid] = rsqrtf(var + EPSB);
        }
        __threadfence();
        __syncthreads();
        if (tid == 0) g_flag = 1;
    }

    if (tid == 0) { while (g_flag == 0) __nanosleep(64); }
    __syncthreads();
    __threadfence();

    #pragma unroll
    for (int rr = 0; rr < 4; rr++) {
        const int idx4 = b * 1024 + rr * 256 + tid;
        const int c4   = idx4 & 31;
        const float4 v  = reinterpret_cast<const float4*>(g_Y)[idx4];
        const float4 mu = reinterpret_cast<const float4*>(g_mu)[c4];
        const float4 rs = reinterpret_cast<const float4*>(g_rstd)[c4];
        const float4 ga = reinterpret_cast<const float4*>(gamma)[c4];
        const float4 be = reinterpret_cast<const float4*>(beta)[c4];
        const float4 bi = reinterpret_cast<const float4*>(bias)[c4];
        float4 r; float o;
        o = fmaf((v.x - mu.x) * rs.x, ga.x, be.x) + bi.x;  r.x = o > 0.f ? o : expm1f(o);
        o = fmaf((v.y - mu.y) * rs.y, ga.y, be.y) + bi.y;  r.y = o > 0.f ? o : expm1f(o);
        o = fmaf((v.z - mu.z) * rs.z, ga.z, be.z) + bi.z;  r.z = o > 0.f ? o : expm1f(o);
        o = fmaf((v.w - mu.w) * rs.w, ga.w, be.w) + bi.w;  r.w = o > 0.f ? o : expm1f(o);
        reinterpret_cast<float4*>(out)[idx4] = r;
    }

    __syncthreads();
    if (tid == 0) {
        if (atomicAdd(&g_done, 1u) == 31u) {
            g_ctr  = 0u;
            g_done = 0u;
            g_flag = 0;
        }
    }
}

// ---------------------------------------------------------------------------
extern "C" void kernel_launch(void* const* d_in, const int* in_sizes, int n_in,
                              void* d_out, int out_size)
{
    const float* x     = (const float*)d_in[0];
    const float* e     = (const float*)d_in[1];
    const float* conn  = (const float*)d_in[2];
    const float* Wp    = (const float*)d_in[3];
    const float* We    = (const float*)d_in[4];
    const float* be    = (const float*)d_in[5];
    const float* asrc  = (const float*)d_in[6];
    const float* atgt  = (const float*)d_in[7];
    const float* aedg  = (const float*)d_in[8];
    const float* Wsk   = (const float*)d_in[9];
    const float* gamma = (const float*)d_in[10];
    const float* beta  = (const float*)d_in[11];
    const float* bias  = (const float*)d_in[12];
    float* out = (float*)d_out;

    k1_proj<<<Nn / 4, 256>>>(x, Wp, Wsk, asrc, atgt, We);
    k2_attn<<<Nn, 256>>>(e, conn, be, aedg);
    k34_bn<<<32, 256>>>(gamma, beta, bias, out);
}

// round 11
// speedup vs baseline: 1.1272x; 1.0292x over previous
#include <cuda_runtime.h>
#include <math.h>

#define Nn    1024
#define Hh    4
#define Ff    32
#define CH    128     // H*F
#define DINC  128
#define DE    32
#define EPSB  1e-5f
#define SLOPE 0.2f

// ---------------- scratch (no allocs allowed) ----------------
__device__ __align__(16) float g_nproj[Nn * CH];
__device__ __align__(16) float g_skip [Nn * CH];
__device__ float g_ssrc [Nn * Hh];
__device__ float g_stgt [Nn * Hh];
__device__ __align__(16) float g_Y    [Nn * CH];
__device__ __align__(16) float g_mu   [CH];
__device__ __align__(16) float g_rstd [CH];
__device__ __align__(16) float g_Wr   [DE * CH];  // [k][lane*4+q] = W_edge[k][q*32+lane]
__device__ float g_p1   [32 * CH];
__device__ float g_p2   [32 * CH];
__device__ unsigned g_ctr;
__device__ unsigned g_done;
__device__ volatile int g_flag;

__device__ __forceinline__ float lrelu(float v) { return v > 0.f ? v : SLOPE * v; }

// ---- Blackwell packed f32x2 helpers ----
__device__ __forceinline__ unsigned long long fma2(unsigned long long a,
                                                   unsigned long long b,
                                                   unsigned long long c) {
    unsigned long long d;
    asm("fma.rn.f32x2 %0, %1, %2, %3;" : "=l"(d) : "l"(a), "l"(b), "l"(c));
    return d;
}
__device__ __forceinline__ unsigned long long dup2(float x) {
    unsigned long long r;
    unsigned xi = __float_as_uint(x);
    asm("mov.b64 %0, {%1, %1};" : "=l"(r) : "r"(xi));
    return r;
}
union U64F2 { unsigned long long u; float2 f; };

// ---------------------------------------------------------------------------
// k1: nproj = x@W_proj, skip = x@W_skip, s_src/s_tgt per-head dots.
// WEIGHTS-STATIONARY: grid 128 x 1024 threads, 8 rows/block.
// Thread (g = tid>>8, c = tid&255): matrix m=c>>7, channel ch=c&127,
// K-group g. W slice (32 floats) loaded into REGISTERS once (MLP 32);
// inner loop is pure LDS-broadcast + packed f32x2 FMA — no LDG at all.
// K-partials combined via smem; head dots from smem. Block 127 also
// swizzles W_edge -> g_Wr for k2.
// ---------------------------------------------------------------------------
__global__ __launch_bounds__(1024, 1) void k1_proj(
    const float* __restrict__ x,
    const float* __restrict__ Wp,
    const float* __restrict__ Wsk,
    const float* __restrict__ a_src,
    const float* __restrict__ a_tgt,
    const float* __restrict__ W_edge)
{
    __shared__ __align__(16) float xs[DINC][8];                 // [k][r]   4 KB
    __shared__ __align__(16) unsigned long long part[4][256][4];// [g][c][pair] 32 KB
    __shared__ float ysm[256][8];                               // combined  8 KB
    const int tid = threadIdx.x;
    const int g   = tid >> 8;         // K-group 0..3
    const int c   = tid & 255;        // 0..255: m = c>>7, ch = c&127
    const int m   = c >> 7;
    const int ch  = c & 127;
    const int i0  = blockIdx.x * 8;

    // ---- W slice into registers (one-time, fully batched LDGs) ----
    const float* __restrict__ Wm = m ? Wsk : Wp;
    const int kbeg = g * 32;
    float wreg[32];
    #pragma unroll
    for (int kk = 0; kk < 32; kk++)
        wreg[kk] = __ldg(&Wm[(kbeg + kk) * CH + ch]);

    // ---- stage x transposed: xs[k][r] = x[i0+r][k] (1 element/thread) ----
    {
        const int r = tid >> 7, k = tid & 127;
        xs[k][r] = x[(i0 + r) * DINC + k];
    }
    if (blockIdx.x == 127) {          // one-time W_edge swizzle for k2
        for (int idx = tid; idx < DE * CH; idx += 1024) {
            const int k = idx >> 7, cc = idx & 127;
            g_Wr[k * CH + (cc & 31) * 4 + (cc >> 5)] = W_edge[idx];
        }
    }
    __syncthreads();

    // ---- main loop: LDS.64 broadcast row-pairs + packed FMA ----
    const unsigned long long* __restrict__ xs2 =
        reinterpret_cast<const unsigned long long*>(xs);   // xs2[k*4+p] = rows {2p,2p+1}
    unsigned long long acc0 = 0ull, acc1 = 0ull, acc2 = 0ull, acc3 = 0ull;
    #pragma unroll
    for (int kk = 0; kk < 32; kk++) {
        const unsigned long long wv = dup2(wreg[kk]);
        const int kb = (kbeg + kk) * 4;
        acc0 = fma2(xs2[kb + 0], wv, acc0);
        acc1 = fma2(xs2[kb + 1], wv, acc1);
        acc2 = fma2(xs2[kb + 2], wv, acc2);
        acc3 = fma2(xs2[kb + 3], wv, acc3);
    }
    part[g][c][0] = acc0;
    part[g][c][1] = acc1;
    part[g][c][2] = acc2;
    part[g][c][3] = acc3;
    __syncthreads();

    // ---- combine 4 K-groups; write outputs; keep in ysm for dots ----
    {
        const int c2 = tid & 255;
        const int rr = tid >> 8;            // 0..3 -> rows rr and rr+4
        const int m2 = c2 >> 7, ch2 = c2 & 127;
        float* __restrict__ dst = m2 ? g_skip : g_nproj;
        #pragma unroll
        for (int hh = 0; hh < 2; hh++) {
            const int r = rr + hh * 4;
            const int p = r >> 1, sel = r & 1;
            U64F2 u0, u1, u2, u3;
            u0.u = part[0][c2][p]; u1.u = part[1][c2][p];
            u2.u = part[2][c2][p]; u3.u = part[3][c2][p];
            const float a = (sel ? u0.f.y : u0.f.x) + (sel ? u1.f.y : u1.f.x)
                          + (sel ? u2.f.y : u2.f.x) + (sel ? u3.f.y : u3.f.x);
            dst[(i0 + r) * CH + ch2] = a;
            ysm[c2][r] = a;
        }
    }
    __syncthreads();

    // ---- head dots: warp w -> (row = w>>2, head = w&3) ----
    {
        const int w    = tid >> 5;
        const int lane = tid & 31;
        const int row  = w >> 2;
        const int hd   = w & 3;
        const int chn  = hd * 32 + lane;          // m=0 channel
        const float yv = ysm[chn][row];
        float s1 = yv * __ldg(&a_src[chn]);
        float s2 = yv * __ldg(&a_tgt[chn]);
        #pragma unroll
        for (int o = 16; o > 0; o >>= 1) {
            s1 += __shfl_xor_sync(0xffffffffu, s1, o);
            s2 += __shfl_xor_sync(0xffffffffu, s2, o);
        }
        if (lane == 0) {
            g_ssrc[(i0 + row) * Hh + hd] = s1;
            g_stgt[(i0 + row) * Hh + hd] = s2;
        }
    }
}

// ---------------------------------------------------------------------------
// k2: per-row sparse attention, one block per row i.
//  - deterministic parallel compaction of active j (conn==0 <=> edge; -1e9
//    edges have bit-exact-zero softmax weight in fp32, matching reference)
//  - 8 warps x 8-edge batches; matvec in packed f32x2 (edge pairs), edges
//    staged in smem so LDS.64 yields packed pairs for free
//  - no max-subtraction softmax (scores O(1)); reduce-and-distribute tree
//    lands sed per head on lane groups -> parallel expf + coalesced
//    LDG.128 nproj gather (4 channels/lane)
// ---------------------------------------------------------------------------
__global__ __launch_bounds__(256) void k2_attn(
    const float* __restrict__ e,
    const float* __restrict__ conn,
    const float* __restrict__ b_edge,
    const float* __restrict__ a_edge)
{
    __shared__ int   jlist[Nn];
    __shared__ int   wcnt[8], woff[8];
    __shared__ int   nact_s;
    __shared__ float ssrc_s[Hh];
    __shared__ __align__(16) float es[8][DE * 10];   // [warp][k*10+b]
    __shared__ float4 acc_sm[8][32];
    __shared__ float  l_sm[8][Hh];

    const int tid  = threadIdx.x;
    const int lane = tid & 31;
    const int w    = tid >> 5;
    const int i    = blockIdx.x;

    if (tid < Hh) ssrc_s[tid] = g_ssrc[i * Hh + tid];

    // --- deterministic compaction: warp w scans j in [w*128, w*128+128) ---
    int  pos[4];
    bool on[4];
    {
        int cnt = 0;
        #pragma unroll
        for (int r = 0; r < 4; r++) {
            const int j = w * 128 + r * 32 + lane;
            on[r] = conn[i * Nn + j] > -1e8f;
            const unsigned bal = __ballot_sync(0xffffffffu, on[r]);
            pos[r] = cnt + __popc(bal & ((1u << lane) - 1u));
            cnt += __popc(bal);
        }
        if (lane == 0) wcnt[w] = cnt;
    }
    __syncthreads();
    if (tid == 0) {
        int acc = 0;
        #pragma unroll
        for (int ww = 0; ww < 8; ww++) { woff[ww] = acc; acc += wcnt[ww]; }
        nact_s = acc;
    }
    __syncthreads();
    {
        const int off = woff[w];
        #pragma unroll
        for (int r = 0; r < 4; r++)
            if (on[r]) jlist[off + pos[r]] = w * 128 + r * 32 + lane;
    }
    __syncthreads();
    const int nact = nact_s;

    const float4* __restrict__ Wr4 = reinterpret_cast<const float4*>(g_Wr);
    const float4 bev = make_float4(b_edge[lane], b_edge[32 + lane],
                                   b_edge[64 + lane], b_edge[96 + lane]);
    const float4 aev = make_float4(a_edge[lane], a_edge[32 + lane],
                                   a_edge[64 + lane], a_edge[96 + lane]);
    const int   head  = lane >> 3;
    const float src_h = ssrc_s[head];
    const bool  hi16  = (lane & 16) != 0;
    const bool  hi8   = (lane & 8)  != 0;

    float4 oacc = make_float4(0.f, 0.f, 0.f, 0.f);
    float  lacc = 0.f;
    float* esw  = es[w];

    for (int base = w * 8; base < nact; base += 64) {
        int  jj[8];
        bool act[8];
        #pragma unroll
        for (int b = 0; b < 8; b++) {
            const int idx = base + b;
            act[b] = idx < nact;
            jj[b]  = jlist[act[b] ? idx : (nact - 1)];
        }

        __syncwarp();
        #pragma unroll
        for (int b = 0; b < 8; b++)
            esw[lane * 10 + b] = __ldg(&e[((long)i * Nn + jj[b]) * DE + lane]);
        __syncwarp();

        unsigned long long acc2[4][4];
        #pragma unroll
        for (int q = 0; q < 4; q++)
            #pragma unroll
            for (int t = 0; t < 4; t++) acc2[q][t] = 0ull;

        #pragma unroll 8
        for (int k = 0; k < DE; k++) {
            const float4 wv = __ldg(&Wr4[k * 32 + lane]);
            const unsigned long long wx = dup2(wv.x), wy = dup2(wv.y),
                                     wz = dup2(wv.z), ww2 = dup2(wv.w);
            #pragma unroll
            for (int t = 0; t < 4; t++) {
                const unsigned long long ee =
                    *reinterpret_cast<const unsigned long long*>(&esw[k * 10 + 2 * t]);
                acc2[0][t] = fma2(ee, wx,  acc2[0][t]);
                acc2[1][t] = fma2(ee, wy,  acc2[1][t]);
                acc2[2][t] = fma2(ee, wz,  acc2[2][t]);
                acc2[3][t] = fma2(ee, ww2, acc2[3][t]);
            }
        }

        #pragma unroll
        for (int b = 0; b < 8; b++) {
            const int t = b >> 1;
            U64F2 c0, c1, c2, c3;
            c0.u = acc2[0][t]; c1.u = acc2[1][t]; c2.u = acc2[2][t]; c3.u = acc2[3][t];
            const float s0 = (b & 1) ? c0.f.y : c0.f.x;
            const float s1 = (b & 1) ? c1.f.y : c1.f.x;
            const float s2 = (b & 1) ? c2.f.y : c2.f.x;
            const float s3 = (b & 1) ? c3.f.y : c3.f.x;

            const float a0 = lrelu(s0 + bev.x) * aev.x;
            const float a1 = lrelu(s1 + bev.y) * aev.y;
            const float a2 = lrelu(s2 + bev.z) * aev.z;
            const float a3 = lrelu(s3 + bev.w) * aev.w;

            float x0 = hi16 ? a2 : a0;
            float x1 = hi16 ? a3 : a1;
            const float y0 = hi16 ? a0 : a2;
            const float y1 = hi16 ? a1 : a3;
            x0 += __shfl_xor_sync(0xffffffffu, y0, 16);
            x1 += __shfl_xor_sync(0xffffffffu, y1, 16);
            float r = (hi8 ? x1 : x0) + __shfl_xor_sync(0xffffffffu, hi8 ? x0 : x1, 8);
            r += __shfl_xor_sync(0xffffffffu, r, 4);
            r += __shfl_xor_sync(0xffffffffu, r, 2);
            r += __shfl_xor_sync(0xffffffffu, r, 1);

            const float stg = __ldg(&g_stgt[jj[b] * Hh + head]);
            const float sc  = lrelu(src_h + stg + r);
            const float p   = act[b] ? __expf(sc) : 0.f;
            lacc += p;
            const float4 nv =
                __ldg(reinterpret_cast<const float4*>(&g_nproj[(long)jj[b] * CH + lane * 4]));
            oacc.x = fmaf(p, nv.x, oacc.x);
            oacc.y = fmaf(p, nv.y, oacc.y);
            oacc.z = fmaf(p, nv.z, oacc.z);
            oacc.w = fmaf(p, nv.w, oacc.w);
        }
    }

    acc_sm[w][lane] = oacc;
    if ((lane & 7) == 0) l_sm[w][head] = lacc;
    __syncthreads();

    if (tid < 32) {
        float4 V = make_float4(0.f, 0.f, 0.f, 0.f);
        float  L = 0.f;
        const int hq = lane >> 3;
        #pragma unroll
        for (int ww = 0; ww < 8; ww++) {
            const float4 a = acc_sm[ww][lane];
            V.x += a.x; V.y += a.y; V.z += a.z; V.w += a.w;
            L   += l_sm[ww][hq];
        }
        const float invL = 1.f / L;
        const float4 sk = *reinterpret_cast<const float4*>(&g_skip[i * CH + lane * 4]);
        float4 yv;
        yv.x = fmaf(V.x, invL, sk.x);
        yv.y = fmaf(V.y, invL, sk.y);
        yv.z = fmaf(V.z, invL, sk.z);
        yv.w = fmaf(V.w, invL, sk.w);
        *reinterpret_cast<float4*>(&g_Y[i * CH + lane * 4]) = yv;
    }
}

// ---------------------------------------------------------------------------
// k34: fused batch-stats + BN apply + ELU. 32 resident blocks, flag spin.
// ---------------------------------------------------------------------------
__global__ __launch_bounds__(256) void k34_bn(
    const float* __restrict__ gamma,
    const float* __restrict__ beta,
    const float* __restrict__ bias,
    float* __restrict__ out)
{
    const int b    = blockIdx.x;
    const int tid  = threadIdx.x;
    const int c    = tid & 127;
    const int half = tid >> 7;

    float s = 0.f, s2 = 0.f;
    const int r0 = b * 32 + half * 16;
    #pragma unroll 4
    for (int r = 0; r < 16; r++) {
        const float v = g_Y[(r0 + r) * CH + c];
        s += v;
        s2 = fmaf(v, v, s2);
    }

    __shared__ float sh1[CH], sh2[CH];
    __shared__ int   amlast;
    if (half == 1) { sh1[c] = s; sh2[c] = s2; }
    __syncthreads();
    if (half == 0) {
        g_p1[b * CH + c] = s  + sh1[c];
        g_p2[b * CH + c] = s2 + sh2[c];
    }
    __threadfence();
    __syncthreads();
    if (tid == 0) amlast = (atomicAdd(&g_ctr, 1u) == 31u);
    __syncthreads();

    if (amlast) {
        if (tid < CH) {
            float S = 0.f, S2 = 0.f;
            #pragma unroll
            for (int bb = 0; bb < 32; bb++) {
                S  += g_p1[bb * CH + tid];
                S2 += g_p2[bb * CH + tid];
            }
            const float mu  = S  * (1.f / Nn);
            const float var = S2 * (1.f / Nn) - mu * mu;
            g_mu[tid]   = mu;
            g_rstd[tid] = rsqrtf(var + EPSB);
        }
        __threadfence();
        __syncthreads();
        if (tid == 0) g_flag = 1;
    }

    if (tid == 0) { while (g_flag == 0) __nanosleep(64); }
    __syncthreads();
    __threadfence();

    #pragma unroll
    for (int rr = 0; rr < 4; rr++) {
        const int idx4 = b * 1024 + rr * 256 + tid;
        const int c4   = idx4 & 31;
        const float4 v  = reinterpret_cast<const float4*>(g_Y)[idx4];
        const float4 mu = reinterpret_cast<const float4*>(g_mu)[c4];
        const float4 rs = reinterpret_cast<const float4*>(g_rstd)[c4];
        const float4 ga = reinterpret_cast<const float4*>(gamma)[c4];
        const float4 be = reinterpret_cast<const float4*>(beta)[c4];
        const float4 bi = reinterpret_cast<const float4*>(bias)[c4];
        float4 r; float o;
        o = fmaf((v.x - mu.x) * rs.x, ga.x, be.x) + bi.x;  r.x = o > 0.f ? o : expm1f(o);
        o = fmaf((v.y - mu.y) * rs.y, ga.y, be.y) + bi.y;  r.y = o > 0.f ? o : expm1f(o);
        o = fmaf((v.z - mu.z) * rs.z, ga.z, be.z) + bi.z;  r.z = o > 0.f ? o : expm1f(o);
        o = fmaf((v.w - mu.w) * rs.w, ga.w, be.w) + bi.w;  r.w = o > 0.f ? o : expm1f(o);
        reinterpret_cast<float4*>(out)[idx4] = r;
    }

    __syncthreads();
    if (tid == 0) {
        if (atomicAdd(&g_done, 1u) == 31u) {
            g_ctr  = 0u;
            g_done = 0u;
            g_flag = 0;
        }
    }
}

// ---------------------------------------------------------------------------
extern "C" void kernel_launch(void* const* d_in, const int* in_sizes, int n_in,
                              void* d_out, int out_size)
{
    const float* x     = (const float*)d_in[0];
    const float* e     = (const float*)d_in[1];
    const float* conn  = (const float*)d_in[2];
    const float* Wp    = (const float*)d_in[3];
    const float* We    = (const float*)d_in[4];
    const float* be    = (const float*)d_in[5];
    const float* asrc  = (const float*)d_in[6];
    const float* atgt  = (const float*)d_in[7];
    const float* aedg  = (const float*)d_in[8];
    const float* Wsk   = (const float*)d_in[9];
    const float* gamma = (const float*)d_in[10];
    const float* beta  = (const float*)d_in[11];
    const float* bias  = (const float*)d_in[12];
    float* out = (float*)d_out;

    k1_proj<<<Nn / 8, 1024>>>(x, Wp, Wsk, asrc, atgt, We);
    k2_attn<<<Nn, 256>>>(e, conn, be, aedg);
    k34_bn<<<32, 256>>>(gamma, beta, bias, out);
}